// round 4
// baseline (speedup 1.0000x reference)
#include <cuda_runtime.h>
#include <cuda_bf16.h>
#include <math.h>

// SimDiff: right[f,i] = cos(x[f,i], x[f+interval, i+1])        (i < tpf-1)
//          down [f,i] = cos(x[f,i], x[f+interval, i+width])    (i < tpf-width)
// all other positions -1. Output: [right_full | down_full], each frames*tpf f32.
//
// LTS-cap analysis: naive per-token warps read every vector 3x through L2
// (490MB), saturating the chip-wide LTS throughput cap (~6300 B/cyc). This
// kernel cuts L2 traffic by capturing reuse in L1:
//   - block = 64 consecutive anchors x 2 consecutive frames (f0, f0+1)
//   - D processed in 512B chunks (dc OUTER) so the reuse window per chunk is
//     ~45KB (resident in the 228KB L1 at 1 block/SM)
//   - within a band: c-target(j) == b-target(j+23)  -> L1 hit
//   - frame chain (interval==1): g=0 targets (frame f0+1) == g=1 anchors -> L1 hit
// Distinct loads per (block,chunk) = 64 + 2*88 = 240 for 384 uses (0.63x).
// Accumulators (4 anchors/warp x 5) live in registers across the chunk loop.

#define EPSN 1e-8f

template <int NPL>  // D = NPL * 128 floats; one chunk = 128 floats = 512B
__global__ void __launch_bounds__(1024, 1) simdiff_band_kernel(
    const float* __restrict__ x,
    const int* __restrict__ p_frames,
    const int* __restrict__ p_height,
    const int* __restrict__ p_width,
    const int* __restrict__ p_interval,
    float* __restrict__ out,
    int total)  // frames * tpf
{
    const int width    = *p_width;
    const int height   = *p_height;
    const int frames   = *p_frames;
    const int interval = *p_interval;
    const int tpf      = width * height;

    const int nb     = (tpf + 63) >> 6;      // 64-anchor bands per frame
    const int fpairs = (frames + 1) >> 1;    // 2-frame groups
    const int npairs = fpairs * nb;

    const int warp = threadIdx.x >> 5;       // 0..31
    const int lane = threadIdx.x & 31;

    float* __restrict__ outR = out;
    float* __restrict__ outD = out + total;
    const float4* __restrict__ x4 = reinterpret_cast<const float4*>(x);
    const int stride4 = NPL * 32;            // float4s per token vector

    for (int p = blockIdx.x; p < npairs; p += gridDim.x) {
        const int fp   = p / nb;
        const int band = p - fp * nb;
        const int s    = band << 6;

        // 4 rounds: r -> (g = r>>1 frame offset, slot = r&1 anchor half).
        // anchor j = s + slot*32 + warp, frame f = 2*fp + g.
        // Invalid loads are clamped to token 0 (always safe); outputs fixed
        // up with -1 in the epilogue.
        int baseA[4], baseB[4], baseC[4];
#pragma unroll
        for (int r = 0; r < 4; r++) {
            const int g = r >> 1, slot = r & 1;
            const int f = 2 * fp + g;
            const int j = s + slot * 32 + warp;
            const bool inr = (f < frames) && (j < tpf);
            const bool va  = inr && (f + interval < frames);
            const bool vr  = va && (j < tpf - 1);
            const bool vd  = va && (j < tpf - width);
            const int  t   = inr ? f * tpf + j : 0;
            const int  bt  = va ? (f + interval) * tpf + j : 0;
            baseA[r] = t * stride4 + lane;
            baseB[r] = (vr ? bt + 1     : bt) * stride4 + lane;
            baseC[r] = (vd ? bt + width : bt) * stride4 + lane;
        }

        float accN[4], accD1[4], accN1[4], accD2[4], accN2[4];
#pragma unroll
        for (int r = 0; r < 4; r++) {
            accN[r] = 0.0f; accD1[r] = 0.0f; accN1[r] = 0.0f;
            accD2[r] = 0.0f; accN2[r] = 0.0f;
        }

#pragma unroll
        for (int dc = 0; dc < NPL; dc++) {
            const int co = dc * 32;
#pragma unroll
            for (int r = 0; r < 4; r++) {
                const float4 a = x4[baseA[r] + co];
                const float4 b = x4[baseB[r] + co];
                const float4 c = x4[baseC[r] + co];
                float na = accN[r], d1 = accD1[r], n1 = accN1[r];
                float d2 = accD2[r], n2 = accN2[r];
                na = fmaf(a.x, a.x, na); na = fmaf(a.y, a.y, na);
                na = fmaf(a.z, a.z, na); na = fmaf(a.w, a.w, na);
                d1 = fmaf(a.x, b.x, d1); d1 = fmaf(a.y, b.y, d1);
                d1 = fmaf(a.z, b.z, d1); d1 = fmaf(a.w, b.w, d1);
                n1 = fmaf(b.x, b.x, n1); n1 = fmaf(b.y, b.y, n1);
                n1 = fmaf(b.z, b.z, n1); n1 = fmaf(b.w, b.w, n1);
                d2 = fmaf(a.x, c.x, d2); d2 = fmaf(a.y, c.y, d2);
                d2 = fmaf(a.z, c.z, d2); d2 = fmaf(a.w, c.w, d2);
                n2 = fmaf(c.x, c.x, n2); n2 = fmaf(c.y, c.y, n2);
                n2 = fmaf(c.z, c.z, n2); n2 = fmaf(c.w, c.w, n2);
                accN[r] = na; accD1[r] = d1; accN1[r] = n1;
                accD2[r] = d2; accN2[r] = n2;
            }
        }

        // Epilogue: per round, warp-reduce 5 values, lane 0 writes.
#pragma unroll
        for (int r = 0; r < 4; r++) {
            float na = accN[r], d1 = accD1[r], n1 = accN1[r];
            float d2 = accD2[r], n2 = accN2[r];
#pragma unroll
            for (int off = 16; off > 0; off >>= 1) {
                na += __shfl_xor_sync(0xFFFFFFFFu, na, off);
                d1 += __shfl_xor_sync(0xFFFFFFFFu, d1, off);
                n1 += __shfl_xor_sync(0xFFFFFFFFu, n1, off);
                d2 += __shfl_xor_sync(0xFFFFFFFFu, d2, off);
                n2 += __shfl_xor_sync(0xFFFFFFFFu, n2, off);
            }
            if (lane == 0) {
                const int g = r >> 1, slot = r & 1;
                const int f = 2 * fp + g;
                const int j = s + slot * 32 + warp;
                if (f < frames && j < tpf) {
                    const bool va = (f + interval < frames);
                    const bool vr = va && (j < tpf - 1);
                    const bool vd = va && (j < tpf - width);
                    const int  t  = f * tpf + j;
                    const float nA = fmaxf(sqrtf(na), EPSN);
                    outR[t] = vr ? d1 / (nA * fmaxf(sqrtf(n1), EPSN)) : -1.0f;
                    outD[t] = vd ? d2 / (nA * fmaxf(sqrtf(n2), EPSN)) : -1.0f;
                }
            }
        }
    }
}

// Generic fallback for arbitrary D (scalar loads, one warp per token).
__global__ void __launch_bounds__(256) simdiff_generic_kernel(
    const float* __restrict__ x,
    const int* __restrict__ p_frames,
    const int* __restrict__ p_height,
    const int* __restrict__ p_width,
    const int* __restrict__ p_interval,
    float* __restrict__ out,
    int total, int D)
{
    const int gwarp = (blockIdx.x * blockDim.x + threadIdx.x) >> 5;
    const int lane  = threadIdx.x & 31;
    if (gwarp >= total) return;

    const int width    = *p_width;
    const int height   = *p_height;
    const int frames   = *p_frames;
    const int interval = *p_interval;
    const int tpf      = width * height;

    const int f = gwarp / tpf;
    const int i = gwarp - f * tpf;

    float* __restrict__ outR = out;
    float* __restrict__ outD = out + total;

    const bool vf = (f + interval) < frames;
    if (!vf) {
        if (lane == 0) { outR[gwarp] = -1.0f; outD[gwarp] = -1.0f; }
        return;
    }
    const bool vr = (i < tpf - 1);
    const bool vd = (i < tpf - width);

    const size_t bframe = (size_t)(f + interval) * tpf + i;
    const size_t i1 = vr ? (bframe + 1)     : bframe;
    const size_t i2 = vd ? (bframe + width) : bframe;

    const float* a = x + (size_t)gwarp * D;
    const float* b = x + i1 * D;
    const float* c = x + i2 * D;

    float na = 0.0f, d1 = 0.0f, n1 = 0.0f, d2 = 0.0f, n2 = 0.0f;
    for (int k = lane; k < D; k += 32) {
        float av = a[k], bv = b[k], cv = c[k];
        na = fmaf(av, av, na);
        d1 = fmaf(av, bv, d1); n1 = fmaf(bv, bv, n1);
        d2 = fmaf(av, cv, d2); n2 = fmaf(cv, cv, n2);
    }

#pragma unroll
    for (int off = 16; off > 0; off >>= 1) {
        na += __shfl_xor_sync(0xFFFFFFFFu, na, off);
        d1 += __shfl_xor_sync(0xFFFFFFFFu, d1, off);
        n1 += __shfl_xor_sync(0xFFFFFFFFu, n1, off);
        d2 += __shfl_xor_sync(0xFFFFFFFFu, d2, off);
        n2 += __shfl_xor_sync(0xFFFFFFFFu, n2, off);
    }

    if (lane == 0) {
        const float nA = fmaxf(sqrtf(na), EPSN);
        outR[gwarp] = vr ? d1 / (nA * fmaxf(sqrtf(n1), EPSN)) : -1.0f;
        outD[gwarp] = vd ? d2 / (nA * fmaxf(sqrtf(n2), EPSN)) : -1.0f;
    }
}

extern "C" void kernel_launch(void* const* d_in, const int* in_sizes, int n_in,
                              void* d_out, int out_size) {
    const float* x        = (const float*)d_in[0];
    const int* p_frames   = (const int*)d_in[1];
    const int* p_height   = (const int*)d_in[2];
    const int* p_width    = (const int*)d_in[3];
    const int* p_interval = (const int*)d_in[4];
    float* out = (float*)d_out;

    const int total = out_size / 2;            // frames * tpf
    const int D     = in_sizes[0] / total;     // hidden dim

    if (D == 1152 || D == 1024 || D == 1280) {
        // Grid-stride over (frame-pair, band) pairs; count is device-derived,
        // so launch a safely-oversized grid (dead blocks exit immediately).
        const int blocks = (total + 127) / 128 + 64;
        if (D == 1152) {
            simdiff_band_kernel<9><<<blocks, 1024>>>(
                x, p_frames, p_height, p_width, p_interval, out, total);
        } else if (D == 1024) {
            simdiff_band_kernel<8><<<blocks, 1024>>>(
                x, p_frames, p_height, p_width, p_interval, out, total);
        } else {
            simdiff_band_kernel<10><<<blocks, 1024>>>(
                x, p_frames, p_height, p_width, p_interval, out, total);
        }
    } else {
        const int blocks = (total + 7) / 8;
        simdiff_generic_kernel<<<blocks, 256>>>(
            x, p_frames, p_height, p_width, p_interval, out, total, D);
    }
}

// round 5
// speedup vs baseline: 1.1221x; 1.1221x over previous
#include <cuda_runtime.h>
#include <cuda_bf16.h>
#include <math.h>

// SimDiff: right[f,i] = cos(x[f,i], x[f+interval, i+1])        (i < tpf-1)
//          down [f,i] = cos(x[f,i], x[f+interval, i+width])    (i < tpf-width)
// all other positions -1. Output: [right_full | down_full], each frames*tpf f32.
//
// Latency-bound regime (nothing at a cap; in-flight-bytes model matches R2
// measurement). Lever = resident warps. One warp per token, 3 streaming
// float4 loads per iteration, register footprint forced <= 32 via
// __launch_bounds__(256, 8) so 64 warps/SM stay resident:
// 64 warps x 3 LDG.128 x 128B ~ 24.6KB in flight/SM -> ~1.55x R2 bandwidth.

#define EPSN 1e-8f

template <int NPL>  // float4 elements per lane; D = NPL * 128
__global__ void __launch_bounds__(256, 8) simdiff_occ_kernel(
    const float* __restrict__ x,
    const int* __restrict__ p_frames,
    const int* __restrict__ p_height,
    const int* __restrict__ p_width,
    const int* __restrict__ p_interval,
    float* __restrict__ out,
    int total)  // frames * tpf
{
    const int gwarp = (blockIdx.x * blockDim.x + threadIdx.x) >> 5;
    const int lane  = threadIdx.x & 31;
    if (gwarp >= total) return;

    const int width    = *p_width;
    const int height   = *p_height;
    const int frames   = *p_frames;
    const int interval = *p_interval;
    const int tpf      = width * height;
    const int D        = NPL * 128;

    const int f = gwarp / tpf;
    const int i = gwarp - f * tpf;

    float* __restrict__ outR = out;
    float* __restrict__ outD = out + total;

    const bool vf = (f + interval) < frames;
    if (!vf) {
        if (lane == 0) { outR[gwarp] = -1.0f; outD[gwarp] = -1.0f; }
        return;
    }
    const bool vr = (i < tpf - 1);
    const bool vd = (i < tpf - width);

    const size_t bframe = (size_t)(f + interval) * tpf + i;
    // Clamp invalid neighbors to a safe in-bounds vector; fixed up at the end.
    const size_t i1 = vr ? (bframe + 1)     : bframe;
    const size_t i2 = vd ? (bframe + width) : bframe;

    // Base pointers; all loop loads are base + compile-time immediate offsets
    // (k unrolled), so no per-iteration address arithmetic registers.
    const float4* __restrict__ a4 =
        reinterpret_cast<const float4*>(x + (size_t)gwarp * D) + lane;
    const float4* __restrict__ b4 =
        reinterpret_cast<const float4*>(x + i1 * D) + lane;
    const float4* __restrict__ c4 =
        reinterpret_cast<const float4*>(x + i2 * D) + lane;

    float na = 0.0f, d1 = 0.0f, n1 = 0.0f, d2 = 0.0f, n2 = 0.0f;

#pragma unroll
    for (int k = 0; k < NPL; k++) {
        const float4 a = a4[32 * k];
        const float4 b = b4[32 * k];
        const float4 c = c4[32 * k];
        na = fmaf(a.x, a.x, na); na = fmaf(a.y, a.y, na);
        na = fmaf(a.z, a.z, na); na = fmaf(a.w, a.w, na);
        d1 = fmaf(a.x, b.x, d1); d1 = fmaf(a.y, b.y, d1);
        d1 = fmaf(a.z, b.z, d1); d1 = fmaf(a.w, b.w, d1);
        n1 = fmaf(b.x, b.x, n1); n1 = fmaf(b.y, b.y, n1);
        n1 = fmaf(b.z, b.z, n1); n1 = fmaf(b.w, b.w, n1);
        d2 = fmaf(a.x, c.x, d2); d2 = fmaf(a.y, c.y, d2);
        d2 = fmaf(a.z, c.z, d2); d2 = fmaf(a.w, c.w, d2);
        n2 = fmaf(c.x, c.x, n2); n2 = fmaf(c.y, c.y, n2);
        n2 = fmaf(c.z, c.z, n2); n2 = fmaf(c.w, c.w, n2);
    }

    // Warp butterfly reduce 5 accumulators.
#pragma unroll
    for (int off = 16; off > 0; off >>= 1) {
        na += __shfl_xor_sync(0xFFFFFFFFu, na, off);
        d1 += __shfl_xor_sync(0xFFFFFFFFu, d1, off);
        n1 += __shfl_xor_sync(0xFFFFFFFFu, n1, off);
        d2 += __shfl_xor_sync(0xFFFFFFFFu, d2, off);
        n2 += __shfl_xor_sync(0xFFFFFFFFu, n2, off);
    }

    if (lane == 0) {
        const float nA = fmaxf(sqrtf(na), EPSN);
        outR[gwarp] = vr ? d1 / (nA * fmaxf(sqrtf(n1), EPSN)) : -1.0f;
        outD[gwarp] = vd ? d2 / (nA * fmaxf(sqrtf(n2), EPSN)) : -1.0f;
    }
}

// Generic fallback for arbitrary D (scalar loads, one warp per token).
__global__ void __launch_bounds__(256) simdiff_generic_kernel(
    const float* __restrict__ x,
    const int* __restrict__ p_frames,
    const int* __restrict__ p_height,
    const int* __restrict__ p_width,
    const int* __restrict__ p_interval,
    float* __restrict__ out,
    int total, int D)
{
    const int gwarp = (blockIdx.x * blockDim.x + threadIdx.x) >> 5;
    const int lane  = threadIdx.x & 31;
    if (gwarp >= total) return;

    const int width    = *p_width;
    const int height   = *p_height;
    const int frames   = *p_frames;
    const int interval = *p_interval;
    const int tpf      = width * height;

    const int f = gwarp / tpf;
    const int i = gwarp - f * tpf;

    float* __restrict__ outR = out;
    float* __restrict__ outD = out + total;

    const bool vf = (f + interval) < frames;
    if (!vf) {
        if (lane == 0) { outR[gwarp] = -1.0f; outD[gwarp] = -1.0f; }
        return;
    }
    const bool vr = (i < tpf - 1);
    const bool vd = (i < tpf - width);

    const size_t bframe = (size_t)(f + interval) * tpf + i;
    const size_t i1 = vr ? (bframe + 1)     : bframe;
    const size_t i2 = vd ? (bframe + width) : bframe;

    const float* a = x + (size_t)gwarp * D;
    const float* b = x + i1 * D;
    const float* c = x + i2 * D;

    float na = 0.0f, d1 = 0.0f, n1 = 0.0f, d2 = 0.0f, n2 = 0.0f;
    for (int k = lane; k < D; k += 32) {
        float av = a[k], bv = b[k], cv = c[k];
        na = fmaf(av, av, na);
        d1 = fmaf(av, bv, d1); n1 = fmaf(bv, bv, n1);
        d2 = fmaf(av, cv, d2); n2 = fmaf(cv, cv, n2);
    }

#pragma unroll
    for (int off = 16; off > 0; off >>= 1) {
        na += __shfl_xor_sync(0xFFFFFFFFu, na, off);
        d1 += __shfl_xor_sync(0xFFFFFFFFu, d1, off);
        n1 += __shfl_xor_sync(0xFFFFFFFFu, n1, off);
        d2 += __shfl_xor_sync(0xFFFFFFFFu, d2, off);
        n2 += __shfl_xor_sync(0xFFFFFFFFu, n2, off);
    }

    if (lane == 0) {
        const float nA = fmaxf(sqrtf(na), EPSN);
        outR[gwarp] = vr ? d1 / (nA * fmaxf(sqrtf(n1), EPSN)) : -1.0f;
        outD[gwarp] = vd ? d2 / (nA * fmaxf(sqrtf(n2), EPSN)) : -1.0f;
    }
}

extern "C" void kernel_launch(void* const* d_in, const int* in_sizes, int n_in,
                              void* d_out, int out_size) {
    const float* x        = (const float*)d_in[0];
    const int* p_frames   = (const int*)d_in[1];
    const int* p_height   = (const int*)d_in[2];
    const int* p_width    = (const int*)d_in[3];
    const int* p_interval = (const int*)d_in[4];
    float* out = (float*)d_out;

    const int total = out_size / 2;            // frames * tpf
    const int D     = in_sizes[0] / total;     // hidden dim

    const int threads = 256;                   // 8 warps/block
    const int blocks  = (total + 7) / 8;

    if (D == 1152) {
        simdiff_occ_kernel<9><<<blocks, threads>>>(
            x, p_frames, p_height, p_width, p_interval, out, total);
    } else if (D == 1024) {
        simdiff_occ_kernel<8><<<blocks, threads>>>(
            x, p_frames, p_height, p_width, p_interval, out, total);
    } else if (D == 1280) {
        simdiff_occ_kernel<10><<<blocks, threads>>>(
            x, p_frames, p_height, p_width, p_interval, out, total);
    } else {
        simdiff_generic_kernel<<<blocks, threads>>>(
            x, p_frames, p_height, p_width, p_interval, out, total, D);
    }
}